// round 12
// baseline (speedup 1.0000x reference)
#include <cuda_runtime.h>
#include <math.h>
#include <stdint.h>

// ---------------- problem constants ----------------
#define BB   32
#define NN   512
#define IND  128
#define HID  256
#define HID2 512
#define HEADS 4
#define HD   64
#define ACT  32
#define TOK  (BB*NN)            // 16384 tokens

// GEMM smem geometry: BK=16, [row][k] stride-20 words, 4-stage pipeline
#define AST  20
#define A_BYTES (128 * AST * 4)            // 10240
#define W_BYTES (64 * AST * 4)             // 5120
#define STAGE_BYTES (A_BYTES + W_BYTES)    // 15360
#define NSTAGE 4
#define GEMM_SMEM_BYTES (NSTAGE * STAGE_BYTES)   // 61440

// ---------------- scratch (device globals) --------
__device__ float g_h1[TOK * HID2];
__device__ float g_hsp[TOK * HID];
__device__ float g_Wh[TOK * HID];
__device__ float g_hl[BB * HEADS * NN];
__device__ float g_hr[BB * HEADS * NN];
__device__ float g_aout[TOK * HID];
__device__ float g_hattn[TOK * HID];
__device__ float g_gg[TOK * 1024];         // merged GRU gates
__device__ float g_q[TOK * HID];
__device__ float g_xc[TOK * IND];
__device__ float g_hidc[TOK * HID];
__device__ float g_htc[TOK * HID];
__device__ float g_wc[860160];
__device__ uint32_t g_mbits[(size_t)BB * NN * (NN / 32)];

// weight offsets in g_wc (floats)
#define WC_ENC1 0
#define WC_ENC2 65536
#define WC_GAT  196608
#define WC_OW   262144
#define WC_SKIP 327680
#define WC_WIH  393216
#define WC_WHH  589824
#define WC_DEC1 786432
#define WC_DEC2 851968

// ---------------- helpers ----------------
__device__ __forceinline__ uint32_t f2tf32(float f) {
    uint32_t r;
    asm("cvt.rna.tf32.f32 %0, %1;" : "=r"(r) : "f"(f));
    return r;
}

__device__ __forceinline__ void mma_tf32(float* d, const uint32_t* a, const uint32_t* b) {
    asm volatile(
        "mma.sync.aligned.m16n8k8.row.col.f32.tf32.tf32.f32 "
        "{%0,%1,%2,%3},{%4,%5,%6,%7},{%8,%9},{%0,%1,%2,%3};"
        : "+f"(d[0]), "+f"(d[1]), "+f"(d[2]), "+f"(d[3])
        : "r"(a[0]), "r"(a[1]), "r"(a[2]), "r"(a[3]),
          "r"(b[0]), "r"(b[1]));
}

__device__ __forceinline__ void ldsm4(uint32_t& r0, uint32_t& r1, uint32_t& r2, uint32_t& r3,
                                      uint32_t addr) {
    asm volatile("ldmatrix.sync.aligned.m8n8.x4.shared.b16 {%0,%1,%2,%3}, [%4];"
                 : "=r"(r0), "=r"(r1), "=r"(r2), "=r"(r3) : "r"(addr));
}

__device__ __forceinline__ void cpa16(uint32_t dst, const void* src, int srcsize) {
    asm volatile("cp.async.ca.shared.global [%0], [%1], 16, %2;"
                 :: "r"(dst), "l"(src), "r"(srcsize) : "memory");
}
#define CP_COMMIT() asm volatile("cp.async.commit_group;" ::: "memory")
#define CP_WAIT2()  asm volatile("cp.async.wait_group 2;" ::: "memory")

// ---------------- merged prep: tf32 conversions + adjacency packing ---------
#define CVT_BLOCKS 3492    // 1787904 float4 / 512
__global__ void prep_kernel(const float* __restrict__ x, const float* __restrict__ hidden,
    const float* __restrict__ w_e1, const float* __restrict__ w_e2,
    const float* __restrict__ w_g,  const float* __restrict__ w_ow,
    const float* __restrict__ w_sk, const float* __restrict__ w_ih,
    const float* __restrict__ w_hh, const float* __restrict__ w_d1,
    const float* __restrict__ w_d2,
    float* __restrict__ xc, float* __restrict__ hidc, float* __restrict__ wc,
    const int* __restrict__ adj, uint32_t* __restrict__ mb)
{
    if (blockIdx.x >= CVT_BLOCKS) {
        int row = blockIdx.x - CVT_BLOCKS;
        int t = threadIdx.x;
        int v = adj[(size_t)row * NN + t];
        unsigned bal = __ballot_sync(0xffffffffu, v != 0);
        if ((t & 31) == 0) mb[row * (NN / 32) + (t >> 5)] = bal;
        return;
    }
    const int NX = 524288, NH = 1048576;
    int i = blockIdx.x * 512 + threadIdx.x;
    const float4* src; float4* dst;
    if (i < NX) { src = (const float4*)x + i; dst = (float4*)xc + i; }
    else if (i < NX + NH) { int j = i - NX; src = (const float4*)hidden + j; dst = (float4*)hidc + j; }
    else {
        int j = i - (NX + NH);
        const float* s; int o;
        if      (j < 16384)  { s = w_e1; o = j; }
        else if (j < 49152)  { s = w_e2; o = j - 16384; }
        else if (j < 65536)  { s = w_g;  o = j - 49152; }
        else if (j < 81920)  { s = w_ow; o = j - 65536; }
        else if (j < 98304)  { s = w_sk; o = j - 81920; }
        else if (j < 147456) { s = w_ih; o = j - 98304; }
        else if (j < 196608) { s = w_hh; o = j - 147456; }
        else if (j < 212992) { s = w_d1; o = j - 196608; }
        else                 { s = w_d2; o = j - 212992; }
        src = (const float4*)s + o; dst = (float4*)wc + j;
    }
    float4 v = *src;
    float4 r;
    r.x = __uint_as_float(f2tf32(v.x));
    r.y = __uint_as_float(f2tf32(v.y));
    r.z = __uint_as_float(f2tf32(v.z));
    r.w = __uint_as_float(f2tf32(v.w));
    *dst = r;
}

// ---------------- segmented TF32 NT GEMM, 4-stage BK=16 pipeline ------------
struct Seg {
    const float *A, *A2, *W, *W2, *b1, *b2;
    int K1, K2, cvt, N;
};

#define ISSUE_TILE(t_) do {                                                    \
    int _t = (t_);                                                             \
    const float* _Ap; const float* _Wp; int _lda, _kof;                        \
    if (_t < nt1) { _Ap = Aq; _Wp = Wq; _lda = K1; _kof = _t * 16; }           \
    else { _Ap = A2q; _Wp = W2q; _lda = K2; _kof = _t * 16 - K1; }             \
    _kof += ac4;                                                               \
    uint32_t _sb = sbase + (_t & 3) * STAGE_BYTES;                             \
    _Pragma("unroll")                                                          \
    for (int _i = 0; _i < 2; _i++)                                             \
        cpa16(_sb + stA[_i], _Ap + (size_t)(m0 + ar + 64 * _i) * _lda + _kof, 16); \
    cpa16(_sb + stB, _Wp + (size_t)(n0l + ar) * _lda + _kof, bvalid);          \
    CP_COMMIT();                                                               \
} while (0)

__global__ void __launch_bounds__(256, 3)
gemm_tf32_kernel(Seg s0, Seg s1, Seg s2, int nb1, int nb2,
                 float* __restrict__ C, int NTOT, int M,
                 const float* __restrict__ lr_a,
                 float* __restrict__ hl, float* __restrict__ hr)
{
    extern __shared__ uint32_t smem[];
    __shared__ float sAL[64], sAR[64];
    __shared__ float sLR[2][128][2];
    const uint32_t sbase = (uint32_t)__cvta_generic_to_shared(smem);

    const int bx = blockIdx.x;
    Seg sg; int nloc;
    if (bx >= nb2)      { sg = s2; nloc = bx - nb2; }
    else if (bx >= nb1) { sg = s1; nloc = bx - nb1; }
    else                { sg = s0; nloc = bx; }
    const float *Aq = sg.A, *A2q = sg.A2, *Wq = sg.W, *W2q = sg.W2;
    const float *b1 = sg.b1, *b2 = sg.b2;
    const int K1 = sg.K1, K2 = sg.K2, cvt = sg.cvt, segN = sg.N;

    const int tid = threadIdx.x;
    const int w = tid >> 5;
    const int lane = tid & 31;
    const int lg = lane >> 2;
    const int lk = lane & 3;
    const int wm = (w >> 1) * 32;
    const int wn = (w & 1) * 32;
    const int m0 = blockIdx.y * 128;
    const int n0g = bx * 64;
    const int n0l = nloc * 64;

    if (lr_a && tid < 128) {
        if (tid < 64) sAL[tid] = lr_a[nloc * 128 + tid];
        else          sAR[tid - 64] = lr_a[nloc * 128 + tid];
    }

    // ldmatrix lane roles
    const int g8 = lane >> 3, r8 = lane & 7;
    const int ghf = g8 >> 1, glf = g8 & 1;

    uint32_t offA[2], offB[2];
#pragma unroll
    for (int im = 0; im < 2; im++)
        offA[im] = (uint32_t)((wm + im * 16 + glf * 8 + r8) * AST + ghf * 4) * 4u;
#pragma unroll
    for (int p = 0; p < 2; p++)
        offB[p] = A_BYTES + (uint32_t)((wn + p * 16 + ghf * 8 + r8) * AST + glf * 4) * 4u;

    // cp.async staging roles: A rows ar, ar+64 (16B each); B row ar
    const int ar = tid >> 2;          // 0..63
    const int ac4 = (tid & 3) * 4;    // word 0,4,8,12
    uint32_t stA[2], stB;
#pragma unroll
    for (int i = 0; i < 2; i++)
        stA[i] = (uint32_t)((ar + 64 * i) * AST + ac4) * 4u;
    stB = A_BYTES + (uint32_t)(ar * AST + ac4) * 4u;
    const int bvalid = (n0l + ar < segN) ? 16 : 0;

    float acc[2][4][4];
#pragma unroll
    for (int i = 0; i < 2; i++)
#pragma unroll
        for (int j = 0; j < 4; j++)
#pragma unroll
            for (int r = 0; r < 4; r++) acc[i][j][r] = 0.f;

    const int nt = (K1 + K2) >> 4;
    const int nt1 = K1 >> 4;

    // prologue: 3 tiles in flight
#pragma unroll
    for (int s = 0; s < 3; s++) {
        if (s < nt) ISSUE_TILE(s);
        else CP_COMMIT();
    }

    for (int t = 0; t < nt; t++) {
        CP_WAIT2();            // tile t complete (3 groups outstanding policy)
        __syncthreads();
        if (t + 3 < nt) ISSUE_TILE(t + 3);
        else CP_COMMIT();

        const uint32_t AbA = sbase + (t & 3) * STAGE_BYTES;
#pragma unroll
        for (int kk = 0; kk < 2; kk++) {
            uint32_t af[2][4];
            uint32_t bf[4][2];
#pragma unroll
            for (int im = 0; im < 2; im++)
                ldsm4(af[im][0], af[im][1], af[im][2], af[im][3],
                      AbA + offA[im] + kk * 32);
#pragma unroll
            for (int p = 0; p < 2; p++)
                ldsm4(bf[2 * p][0], bf[2 * p][1], bf[2 * p + 1][0], bf[2 * p + 1][1],
                      AbA + offB[p] + kk * 32);
#pragma unroll
            for (int im = 0; im < 2; im++)
#pragma unroll
                for (int jn = 0; jn < 4; jn++)
                    mma_tf32(acc[im][jn], af[im], bf[jn]);
        }
    }

    // ---- epilogue (+ optional lr dot accumulation) ----
    float pl[2][2] = {{0.f, 0.f}, {0.f, 0.f}};
    float pr[2][2] = {{0.f, 0.f}, {0.f, 0.f}};
#pragma unroll
    for (int im = 0; im < 2; im++) {
#pragma unroll
        for (int jn = 0; jn < 4; jn++) {
            int colL = wn + jn * 8 + 2 * lk;
            if (n0l + colL >= segN) continue;
            float bias0 = 0.f, bias1 = 0.f;
            if (b1) { bias0 += b1[n0l + colL]; bias1 += b1[n0l + colL + 1]; }
            if (b2) { bias0 += b2[n0l + colL]; bias1 += b2[n0l + colL + 1]; }
#pragma unroll
            for (int half = 0; half < 2; half++) {
                int row = m0 + wm + im * 16 + lg + half * 8;
                float v0 = acc[im][jn][half * 2 + 0] + bias0;
                float v1 = acc[im][jn][half * 2 + 1] + bias1;
                if (lr_a) {
                    pl[im][half] += v0 * sAL[colL] + v1 * sAL[colL + 1];
                    pr[im][half] += v0 * sAR[colL] + v1 * sAR[colL + 1];
                }
                if (cvt) {
                    v0 = __uint_as_float(f2tf32(v0));
                    v1 = __uint_as_float(f2tf32(v1));
                }
                *reinterpret_cast<float2*>(C + (size_t)row * NTOT + n0g + colL)
                    = make_float2(v0, v1);
            }
        }
    }

    if (lr_a) {
#pragma unroll
        for (int im = 0; im < 2; im++)
#pragma unroll
            for (int half = 0; half < 2; half++) {
                pl[im][half] += __shfl_xor_sync(0xffffffffu, pl[im][half], 1);
                pl[im][half] += __shfl_xor_sync(0xffffffffu, pl[im][half], 2);
                pr[im][half] += __shfl_xor_sync(0xffffffffu, pr[im][half], 1);
                pr[im][half] += __shfl_xor_sync(0xffffffffu, pr[im][half], 2);
            }
        if (lk == 0) {
#pragma unroll
            for (int im = 0; im < 2; im++)
#pragma unroll
                for (int half = 0; half < 2; half++) {
                    int rl = wm + im * 16 + lg + half * 8;
                    sLR[0][rl][w & 1] = pl[im][half];
                    sLR[1][rl][w & 1] = pr[im][half];
                }
        }
        __syncthreads();
        int s = tid >> 7;
        int row = tid & 127;
        float v = sLR[s][row][0] + sLR[s][row][1];
        int grow = m0 + row;
        int bidx = grow >> 9;
        int ii = grow & 511;
        float* dst = s ? hr : hl;
        dst[((bidx * HEADS + nloc) << 9) + ii] = v;
    }
}

// ---------------- fast exact GELU (A&S 7.1.26 erf, abs err ~1.5e-7) ---------
__device__ __forceinline__ float gelu_fast(float x) {
    float s = x * 0.70710678118654752440f;
    float a = fabsf(s);
    float t = __frcp_rn(1.0f + 0.3275911f * a);
    float e = __expf(-a * a);
    float p = ((((1.061405429f * t - 1.453152027f) * t + 1.421413741f) * t
                - 0.284496736f) * t + 0.254829592f) * t;
    float erfv = copysignf(1.0f - p * e, s);
    return 0.5f * x * (1.0f + erfv);
}

__global__ void ln_gelu_kernel(float* __restrict__ X,
                               const float* __restrict__ g,
                               const float* __restrict__ b,
                               int D)
{
    __shared__ float sS[8], sQ[8];
    float* row = X + (size_t)blockIdx.x * D;
    const int t = threadIdx.x;
    const int w = t >> 5;
    const int lane = t & 31;

    float v0 = row[t];
    float v1 = (D > 256) ? row[t + 256] : 0.f;

    float s = v0 + v1;
    float q = v0 * v0 + v1 * v1;
#pragma unroll
    for (int o = 16; o; o >>= 1) {
        s += __shfl_xor_sync(0xffffffffu, s, o);
        q += __shfl_xor_sync(0xffffffffu, q, o);
    }
    if (lane == 0) { sS[w] = s; sQ[w] = q; }
    __syncthreads();
    float ts = 0.f, tq = 0.f;
#pragma unroll
    for (int i = 0; i < 8; i++) { ts += sS[i]; tq += sQ[i]; }
    float mean = ts / (float)D;
    float var = tq / (float)D - mean * mean;
    float rstd = rsqrtf(var + 1e-5f);

    row[t] = __uint_as_float(f2tf32(gelu_fast((v0 - mean) * rstd * g[t] + b[t])));
    if (D > 256)
        row[t + 256] = __uint_as_float(f2tf32(gelu_fast((v1 - mean) * rstd * g[t + 256] + b[t + 256])));
}

// ---------------- GAT attention: exp-factorized + tf32 MMA, double-buffered -
__global__ void gat_attn_mma_kernel(const float* __restrict__ Wh,
                                    const float* __restrict__ hl,
                                    const float* __restrict__ hr,
                                    const uint32_t* __restrict__ mb,
                                    float* __restrict__ out)
{
    __shared__ float4 sJF[NN];
    __shared__ float sA1[128], sA2[128], sNL[128];
    __shared__ uint4 sP[2][4 * 8 * 32];
    __shared__ uint32_t sW[2][32][68];
    __shared__ float sS[128];
    __shared__ float sRed[16];
    __shared__ float sMax[2];

    const int bx = blockIdx.x;
    const int it = bx & 3;
    const int h = (bx >> 2) & 3;
    const int b = bx >> 4;
    const int tid = threadIdx.x;
    const int w = tid >> 5;
    const int lane = tid & 31;
    const int lg = lane >> 2;
    const int lk = lane & 3;
    const int bh = b * HEADS + h;
    const int i0 = it * 128;

    float lv = 0.f;
    if (tid < 128) lv = hl[(bh << 9) + i0 + tid];
    float rv0 = hr[(bh << 9) + tid];
    float rv1 = hr[(bh << 9) + 256 + tid];

    float lm = (tid < 128) ? lv : -INFINITY;
    float rm = fmaxf(rv0, rv1);
#pragma unroll
    for (int o = 16; o; o >>= 1) {
        lm = fmaxf(lm, __shfl_xor_sync(0xffffffffu, lm, o));
        rm = fmaxf(rm, __shfl_xor_sync(0xffffffffu, rm, o));
    }
    if (lane == 0) { sRed[w] = lm; sRed[8 + w] = rm; }
    __syncthreads();
    if (tid == 0) {
        float L = -INFINITY, R = -INFINITY;
#pragma unroll
        for (int qq = 0; qq < 8; qq++) { L = fmaxf(L, sRed[qq]); R = fmaxf(R, sRed[8 + qq]); }
        sMax[0] = L; sMax[1] = R;
    }
    __syncthreads();
    const float Lmax = sMax[0], Rmax = sMax[1];
    const float C1 = Lmax + Rmax;

    sJF[tid]       = make_float4(rv0, expf(rv0 - Rmax), expf(0.2f * rv0), 0.f);
    sJF[tid + 256] = make_float4(rv1, expf(rv1 - Rmax), expf(0.2f * rv1), 0.f);
    if (tid < 128) {
        sA1[tid] = expf(lv - Lmax);
        sA2[tid] = expf(0.2f * lv - C1);
        sNL[tid] = -lv;
    }
    __syncthreads();

    const int r0 = w * 16 + lg;
    const int r1 = r0 + 8;
    const float A1a = sA1[r0], A2a = sA2[r0], NLa = sNL[r0];
    const float A1b = sA1[r1], A2b = sA2[r1], NLb = sNL[r1];
    const uint32_t* mrow0 = mb + ((size_t)(b << 9) + i0 + r0) * (NN / 32);
    const uint32_t* mrow1 = mb + ((size_t)(b << 9) + i0 + r1) * (NN / 32);
    float psum0 = 0.f, psum1 = 0.f;

    const int wm16 = (w >> 1) * 2;
    const int wn = (w & 1) * 32;
    float acc[2][4][4];
#pragma unroll
    for (int i = 0; i < 2; i++)
#pragma unroll
        for (int j = 0; j < 4; j++)
#pragma unroll
            for (int r = 0; r < 4; r++) acc[i][j][r] = 0.f;

    const float* whbase = Wh + (size_t)b * NN * HID + h * HD;

    for (int jt = 0; jt < 16; jt++) {
        const int buf = jt & 1;
        // ---- build phase (into buf) ----
#pragma unroll
        for (int itr = 0; itr < 2; itr++) {
            int f = tid + 256 * itr;
            int jp = f >> 4;
            int dq = (f & 15) * 4;
            float4 v = *reinterpret_cast<const float4*>(whbase + (size_t)(jt * 32 + jp) * HID + dq);
            sW[buf][jp][dq + 0] = f2tf32(v.x);
            sW[buf][jp][dq + 1] = f2tf32(v.y);
            sW[buf][jp][dq + 2] = f2tf32(v.z);
            sW[buf][jp][dq + 3] = f2tf32(v.w);
        }
        uint32_t mw0 = mrow0[jt];
        uint32_t mw1 = mrow1[jt];
#pragma unroll
        for (int kk = 0; kk < 4; kk++) {
            int c0 = kk * 8 + lk;
            int c1 = c0 + 4;
            float4 jf0 = sJF[jt * 32 + c0];
            float4 jf1 = sJF[jt * 32 + c1];
            bool cd00 = (jf0.x >= NLa), cd10 = (jf0.x >= NLb);
            bool cd01 = (jf1.x >= NLa), cd11 = (jf1.x >= NLb);
            float p00 = ((mw0 >> c0) & 1) ? (cd00 ? A1a * jf0.y : A2a * jf0.z) : 0.f;
            float p10 = ((mw1 >> c0) & 1) ? (cd10 ? A1b * jf0.y : A2b * jf0.z) : 0.f;
            float p01 = ((mw0 >> c1) & 1) ? (cd01 ? A1a * jf1.y : A2a * jf1.z) : 0.f;
            float p11 = ((mw1 >> c1) & 1) ? (cd11 ? A1b * jf1.y : A2b * jf1.z) : 0.f;
            psum0 += p00 + p01;
            psum1 += p10 + p11;
            uint4 pk;
            pk.x = f2tf32(p00);
            pk.y = f2tf32(p10);
            pk.z = f2tf32(p01);
            pk.w = f2tf32(p11);
            sP[buf][(kk * 8 + w) * 32 + lane] = pk;
        }
        __syncthreads();

        // ---- MMA phase (from buf) ----
#pragma unroll
        for (int kk = 0; kk < 4; kk++) {
            uint4 av[2];
#pragma unroll
            for (int im = 0; im < 2; im++)
                av[im] = sP[buf][(kk * 8 + wm16 + im) * 32 + lane];
#pragma unroll
            for (int jn = 0; jn < 4; jn++) {
                int nc = wn + jn * 8 + lg;
                uint32_t bf[2];
                bf[0] = sW[buf][kk * 8 + lk][nc];
                bf[1] = sW[buf][kk * 8 + 4 + lk][nc];
#pragma unroll
                for (int im = 0; im < 2; im++)
                    mma_tf32(acc[im][jn],
                             reinterpret_cast<const uint32_t*>(&av[im]), bf);
            }
        }
        // no second barrier: double buffering makes build(jt+2) safe
    }

    psum0 += __shfl_xor_sync(0xffffffffu, psum0, 1);
    psum0 += __shfl_xor_sync(0xffffffffu, psum0, 2);
    psum1 += __shfl_xor_sync(0xffffffffu, psum1, 1);
    psum1 += __shfl_xor_sync(0xffffffffu, psum1, 2);
    if (lk == 0) { sS[r0] = psum0; sS[r1] = psum1; }
    __syncthreads();

#pragma unroll
    for (int im = 0; im < 2; im++) {
#pragma unroll
        for (int half = 0; half < 2; half++) {
            int rloc = (w >> 1) * 32 + im * 16 + lg + half * 8;
            float inv = 1.f / sS[rloc];
            int grow = (b << 9) + i0 + rloc;
#pragma unroll
            for (int jn = 0; jn < 4; jn++) {
                int col = wn + jn * 8 + 2 * lk;
                float2* dst = reinterpret_cast<float2*>(out + (size_t)grow * HID + h * HD + col);
                *dst = make_float2(
                    __uint_as_float(f2tf32(acc[im][jn][half * 2 + 0] * inv)),
                    __uint_as_float(f2tf32(acc[im][jn][half * 2 + 1] * inv)));
            }
        }
    }
}

// ---------------- GRU gates -> h_temp (fp32 out + tf32 copy) ----------
__global__ void gru_kernel(const float* __restrict__ gg,
                           const float* __restrict__ hidden,
                           float* __restrict__ h_temp,
                           float* __restrict__ htc)
{
    int idx = blockIdx.x * blockDim.x + threadIdx.x;
    if (idx >= TOK * HID) return;
    int row = idx >> 8;
    int c = idx & 255;
    const float* g = gg + ((size_t)row << 10);
    float r = __frcp_rn(1.f + __expf(-g[c]));
    float z = __frcp_rn(1.f + __expf(-g[256 + c]));
    float n = tanhf(g[512 + c] + r * g[768 + c]);
    float v = (1.f - z) * n + z * hidden[idx];
    h_temp[idx] = v;
    htc[idx] = __uint_as_float(f2tf32(v));
}

// ---------------- launch ----------------
extern "C" void kernel_launch(void* const* d_in, const int* in_sizes, int n_in,
                              void* d_out, int out_size)
{
    const float* x        = (const float*)d_in[0];
    const int*   adj      = (const int*)  d_in[1];
    const float* hidden   = (const float*)d_in[2];
    const float* enc_w1   = (const float*)d_in[3];
    const float* enc_b1   = (const float*)d_in[4];
    const float* ln1_g    = (const float*)d_in[5];
    const float* ln1_b    = (const float*)d_in[6];
    const float* enc_w2   = (const float*)d_in[7];
    const float* enc_b2   = (const float*)d_in[8];
    const float* pos      = (const float*)d_in[9];
    const float* gat_w    = (const float*)d_in[10];
    const float* gat_b    = (const float*)d_in[11];
    const float* gat_a    = (const float*)d_in[12];
    const float* gat_ow   = (const float*)d_in[13];
    const float* gat_ob   = (const float*)d_in[14];
    const float* skip_w   = (const float*)d_in[15];
    const float* skip_b   = (const float*)d_in[16];
    const float* gru_wih  = (const float*)d_in[17];
    const float* gru_bih  = (const float*)d_in[18];
    const float* gru_whh  = (const float*)d_in[19];
    const float* gru_bhh  = (const float*)d_in[20];
    const float* dec_w1   = (const float*)d_in[21];
    const float* dec_b1   = (const float*)d_in[22];
    const float* ln2_g    = (const float*)d_in[23];
    const float* ln2_b    = (const float*)d_in[24];
    const float* dec_w2   = (const float*)d_in[25];
    const float* dec_b2   = (const float*)d_in[26];

    float* out = (float*)d_out;
    float* q_out = out;
    float* h_temp_out = out + (size_t)TOK * ACT;

    float *h1, *hsp, *Wh, *hl, *hr, *aout, *hattn, *gg, *q;
    float *xc, *hidc, *htc, *wc;
    uint32_t* mbits;
    cudaGetSymbolAddress((void**)&h1,    g_h1);
    cudaGetSymbolAddress((void**)&hsp,   g_hsp);
    cudaGetSymbolAddress((void**)&Wh,    g_Wh);
    cudaGetSymbolAddress((void**)&hl,    g_hl);
    cudaGetSymbolAddress((void**)&hr,    g_hr);
    cudaGetSymbolAddress((void**)&aout,  g_aout);
    cudaGetSymbolAddress((void**)&hattn, g_hattn);
    cudaGetSymbolAddress((void**)&gg,    g_gg);
    cudaGetSymbolAddress((void**)&q,     g_q);
    cudaGetSymbolAddress((void**)&xc,    g_xc);
    cudaGetSymbolAddress((void**)&hidc,  g_hidc);
    cudaGetSymbolAddress((void**)&htc,   g_htc);
    cudaGetSymbolAddress((void**)&wc,    g_wc);
    cudaGetSymbolAddress((void**)&mbits, g_mbits);

    cudaFuncSetAttribute(gemm_tf32_kernel,
                         cudaFuncAttributeMaxDynamicSharedMemorySize,
                         GEMM_SMEM_BYTES);

    const int MB = TOK / 128;
    const size_t SH = GEMM_SMEM_BYTES;
    Seg Z = { nullptr, nullptr, nullptr, nullptr, nullptr, nullptr, 0, 0, 0, 0 };

    prep_kernel<<<CVT_BLOCKS + TOK, 512>>>(
        x, hidden, enc_w1, enc_w2, gat_w, gat_ow, skip_w, gru_wih, gru_whh,
        dec_w1, dec_w2, xc, hidc, wc, adj, mbits);

    // encoder
    {
        Seg s = { xc, nullptr, wc + WC_ENC1, nullptr, enc_b1, nullptr, IND, 0, 0, HID2 };
        gemm_tf32_kernel<<<dim3(8, MB), 256, SH>>>(s, Z, Z, 8, 8, h1, HID2, TOK,
                                                   nullptr, nullptr, nullptr);
    }
    ln_gelu_kernel<<<TOK, 256>>>(h1, ln1_g, ln1_b, HID2);
    {
        Seg s = { h1, nullptr, wc + WC_ENC2, nullptr, enc_b2, pos, HID2, 0, 1, HID };
        gemm_tf32_kernel<<<dim3(4, MB), 256, SH>>>(s, Z, Z, 4, 4, hsp, HID, TOK,
                                                   nullptr, nullptr, nullptr);
    }

    // GAT projection + fused l/r scores
    {
        Seg s = { hsp, nullptr, wc + WC_GAT, nullptr, gat_b, nullptr, HID, 0, 1, HID };
        gemm_tf32_kernel<<<dim3(4, MB), 256, SH>>>(s, Z, Z, 4, 4, Wh, HID, TOK,
                                                   gat_a, hl, hr);
    }
    gat_attn_mma_kernel<<<BB * HEADS * 4, 256>>>(Wh, hl, hr, mbits, aout);

    // fused out-proj + skip
    {
        Seg s = { aout, hsp, wc + WC_OW, wc + WC_SKIP, gat_ob, skip_b, HID, HID, 1, HID };
        gemm_tf32_kernel<<<dim3(4, MB), 256, SH>>>(s, Z, Z, 4, 4, hattn, HID, TOK,
                                                   nullptr, nullptr, nullptr);
    }

    // merged GRU GEMM
    {
        Seg s0 = { hattn, hidc, wc + WC_WIH, wc + WC_WHH, gru_bih, gru_bhh,
                   HID, HID, 0, HID2 };
        Seg s1 = { hattn, nullptr, wc + WC_WIH + 2 * HID * HID, nullptr,
                   gru_bih + 2 * HID, nullptr, HID, 0, 0, HID };
        Seg s2 = { hidc, nullptr, wc + WC_WHH + 2 * HID * HID, nullptr,
                   gru_bhh + 2 * HID, nullptr, HID, 0, 0, HID };
        gemm_tf32_kernel<<<dim3(16, MB), 256, SH>>>(s0, s1, s2, 8, 12, gg, 1024, TOK,
                                                    nullptr, nullptr, nullptr);
    }
    gru_kernel<<<(TOK * HID + 255) / 256, 256>>>(gg, hidden, h_temp_out, htc);

    // decoder
    {
        Seg s = { htc, nullptr, wc + WC_DEC1, nullptr, dec_b1, nullptr, HID, 0, 0, HID };
        gemm_tf32_kernel<<<dim3(4, MB), 256, SH>>>(s, Z, Z, 4, 4, q, HID, TOK,
                                                   nullptr, nullptr, nullptr);
    }
    ln_gelu_kernel<<<TOK, 256>>>(q, ln2_g, ln2_b, HID);
    {
        Seg s = { q, nullptr, wc + WC_DEC2, nullptr, dec_b2, nullptr, HID, 0, 0, ACT };
        gemm_tf32_kernel<<<dim3(1, MB), 256, SH>>>(s, Z, Z, 1, 1, q_out, ACT, TOK,
                                                   nullptr, nullptr, nullptr);
    }
}

// round 13
// speedup vs baseline: 1.6799x; 1.6799x over previous
#include <cuda_runtime.h>
#include <math.h>
#include <stdint.h>

// ---------------- problem constants ----------------
#define BB   32
#define NN   512
#define IND  128
#define HID  256
#define HID2 512
#define HEADS 4
#define HD   64
#define ACT  32
#define TOK  (BB*NN)            // 16384 tokens

// GEMM smem geometry: [row][k] stride-36 words, double buffered (BK=32)
#define AST  36
#define A_WORDS (128 * AST)
#define W_WORDS (64 * AST)
#define A_BYTES (A_WORDS * 4)
#define STAGE_BYTES ((A_WORDS + W_WORDS) * 4)     // 27648
#define GEMM_SMEM_BYTES (2 * STAGE_BYTES)         // 55296

// ---------------- scratch (device globals) --------
__device__ float g_h1[TOK * HID2];
__device__ float g_hsp[TOK * HID];
__device__ float g_Wh[TOK * HID];
__device__ float g_hl[BB * HEADS * NN];
__device__ float g_hr[BB * HEADS * NN];
__device__ float g_aout[TOK * HID];
__device__ float g_hattn[TOK * HID];
__device__ float g_gg[TOK * 1024];         // merged GRU gates
__device__ float g_q[TOK * HID];
__device__ float g_xc[TOK * IND];
__device__ float g_hidc[TOK * HID];
__device__ float g_htc[TOK * HID];
__device__ float g_wc[860160];
__device__ uint32_t g_mbits[(size_t)BB * NN * (NN / 32)];

// weight offsets in g_wc (floats)
#define WC_ENC1 0
#define WC_ENC2 65536
#define WC_GAT  196608
#define WC_OW   262144
#define WC_SKIP 327680
#define WC_WIH  393216
#define WC_WHH  589824
#define WC_DEC1 786432
#define WC_DEC2 851968

// ---------------- helpers ----------------
__device__ __forceinline__ uint32_t f2tf32(float f) {
    uint32_t r;
    asm("cvt.rna.tf32.f32 %0, %1;" : "=r"(r) : "f"(f));
    return r;
}

__device__ __forceinline__ void mma_tf32(float* d, const uint32_t* a, const uint32_t* b) {
    asm volatile(
        "mma.sync.aligned.m16n8k8.row.col.f32.tf32.tf32.f32 "
        "{%0,%1,%2,%3},{%4,%5,%6,%7},{%8,%9},{%0,%1,%2,%3};"
        : "+f"(d[0]), "+f"(d[1]), "+f"(d[2]), "+f"(d[3])
        : "r"(a[0]), "r"(a[1]), "r"(a[2]), "r"(a[3]),
          "r"(b[0]), "r"(b[1]));
}

__device__ __forceinline__ void ldsm4(uint32_t& r0, uint32_t& r1, uint32_t& r2, uint32_t& r3,
                                      uint32_t addr) {
    asm volatile("ldmatrix.sync.aligned.m8n8.x4.shared.b16 {%0,%1,%2,%3}, [%4];"
                 : "=r"(r0), "=r"(r1), "=r"(r2), "=r"(r3) : "r"(addr));
}

__device__ __forceinline__ void cpa16(uint32_t dst, const void* src, int srcsize) {
    asm volatile("cp.async.ca.shared.global [%0], [%1], 16, %2;"
                 :: "r"(dst), "l"(src), "r"(srcsize) : "memory");
}
#define CP_COMMIT() asm volatile("cp.async.commit_group;" ::: "memory")
#define CP_WAIT0()  asm volatile("cp.async.wait_group 0;" ::: "memory")

// ---------------- merged prep: tf32 conversions + adjacency packing ---------
#define CVT_BLOCKS 3492    // 1787904 float4 / 512
__global__ void prep_kernel(const float* __restrict__ x, const float* __restrict__ hidden,
    const float* __restrict__ w_e1, const float* __restrict__ w_e2,
    const float* __restrict__ w_g,  const float* __restrict__ w_ow,
    const float* __restrict__ w_sk, const float* __restrict__ w_ih,
    const float* __restrict__ w_hh, const float* __restrict__ w_d1,
    const float* __restrict__ w_d2,
    float* __restrict__ xc, float* __restrict__ hidc, float* __restrict__ wc,
    const int* __restrict__ adj, uint32_t* __restrict__ mb)
{
    if (blockIdx.x >= CVT_BLOCKS) {
        int row = blockIdx.x - CVT_BLOCKS;
        int t = threadIdx.x;
        int v = adj[(size_t)row * NN + t];
        unsigned bal = __ballot_sync(0xffffffffu, v != 0);
        if ((t & 31) == 0) mb[row * (NN / 32) + (t >> 5)] = bal;
        return;
    }
    const int NX = 524288, NH = 1048576;
    int i = blockIdx.x * 512 + threadIdx.x;
    const float4* src; float4* dst;
    if (i < NX) { src = (const float4*)x + i; dst = (float4*)xc + i; }
    else if (i < NX + NH) { int j = i - NX; src = (const float4*)hidden + j; dst = (float4*)hidc + j; }
    else {
        int j = i - (NX + NH);
        const float* s; int o;
        if      (j < 16384)  { s = w_e1; o = j; }
        else if (j < 49152)  { s = w_e2; o = j - 16384; }
        else if (j < 65536)  { s = w_g;  o = j - 49152; }
        else if (j < 81920)  { s = w_ow; o = j - 65536; }
        else if (j < 98304)  { s = w_sk; o = j - 81920; }
        else if (j < 147456) { s = w_ih; o = j - 98304; }
        else if (j < 196608) { s = w_hh; o = j - 147456; }
        else if (j < 212992) { s = w_d1; o = j - 196608; }
        else                 { s = w_d2; o = j - 212992; }
        src = (const float4*)s + o; dst = (float4*)wc + j;
    }
    float4 v = *src;
    float4 r;
    r.x = __uint_as_float(f2tf32(v.x));
    r.y = __uint_as_float(f2tf32(v.y));
    r.z = __uint_as_float(f2tf32(v.z));
    r.w = __uint_as_float(f2tf32(v.w));
    *dst = r;
}

// ---------------- segmented TF32 NT GEMM (BK=32, 2-stage, R8 design) --------
struct Seg {
    const float *A, *A2, *W, *W2, *b1, *b2;
    int K1, K2, cvt, N;
};

#define ISSUE_TILE(t_) do {                                                    \
    int _t = (t_);                                                             \
    const float* _Ap; const float* _Wp; int _lda, _kof;                        \
    if (_t < nt1) { _Ap = Aq; _Wp = Wq; _lda = K1; _kof = _t * 32; }           \
    else { _Ap = A2q; _Wp = W2q; _lda = K2; _kof = _t * 32 - K1; }             \
    _kof += ac4;                                                               \
    uint32_t _sb = sbase + (_t & 1) * STAGE_BYTES;                             \
    _Pragma("unroll")                                                          \
    for (int _i = 0; _i < 4; _i++)                                             \
        cpa16(_sb + stA[_i], _Ap + (size_t)(m0 + ar + 32 * _i) * _lda + _kof, 16); \
    _Pragma("unroll")                                                          \
    for (int _i = 0; _i < 2; _i++)                                             \
        cpa16(_sb + stB[_i], _Wp + (size_t)(n0l + ar + 32 * _i) * _lda + _kof, bvalid[_i]); \
    CP_COMMIT();                                                               \
} while (0)

__global__ void __launch_bounds__(256, 3)
gemm_tf32_kernel(Seg s0, Seg s1, Seg s2, int nb1, int nb2,
                 float* __restrict__ C, int NTOT, int M,
                 const float* __restrict__ lr_a,
                 float* __restrict__ hl, float* __restrict__ hr)
{
    extern __shared__ uint32_t smem[];
    __shared__ float sAL[64], sAR[64];
    __shared__ float sLR[2][128][2];
    const uint32_t sbase = (uint32_t)__cvta_generic_to_shared(smem);

    const int bx = blockIdx.x;
    Seg sg; int nloc;
    if (bx >= nb2)      { sg = s2; nloc = bx - nb2; }
    else if (bx >= nb1) { sg = s1; nloc = bx - nb1; }
    else                { sg = s0; nloc = bx; }
    const float *Aq = sg.A, *A2q = sg.A2, *Wq = sg.W, *W2q = sg.W2;
    const float *b1 = sg.b1, *b2 = sg.b2;
    const int K1 = sg.K1, K2 = sg.K2, cvt = sg.cvt, segN = sg.N;

    const int tid = threadIdx.x;
    const int w = tid >> 5;
    const int lane = tid & 31;
    const int lg = lane >> 2;
    const int lk = lane & 3;
    const int wm = (w >> 1) * 32;
    const int wn = (w & 1) * 32;
    const int m0 = blockIdx.y * 128;
    const int n0g = bx * 64;
    const int n0l = nloc * 64;

    if (lr_a && tid < 128) {
        if (tid < 64) sAL[tid] = lr_a[nloc * 128 + tid];
        else          sAR[tid - 64] = lr_a[nloc * 128 + tid];
    }

    // ldmatrix lane roles
    const int g8 = lane >> 3, r8 = lane & 7;
    const int ghf = g8 >> 1, glf = g8 & 1;

    uint32_t offA[2], offB[2];
#pragma unroll
    for (int im = 0; im < 2; im++)
        offA[im] = (uint32_t)((wm + im * 16 + glf * 8 + r8) * AST + ghf * 4) * 4u;
#pragma unroll
    for (int p = 0; p < 2; p++)
        offB[p] = A_BYTES + (uint32_t)((wn + p * 16 + ghf * 8 + r8) * AST + glf * 4) * 4u;

    // cp.async staging roles
    const int ar = tid >> 3;
    const int ac4 = (tid & 7) * 4;
    uint32_t stA[4], stB[2];
    int bvalid[2];
#pragma unroll
    for (int i = 0; i < 4; i++)
        stA[i] = (uint32_t)((ar + 32 * i) * AST + ac4) * 4u;
#pragma unroll
    for (int i = 0; i < 2; i++) {
        stB[i] = A_BYTES + (uint32_t)((ar + 32 * i) * AST + ac4) * 4u;
        bvalid[i] = (n0l + ar + 32 * i < segN) ? 16 : 0;
    }

    float acc[2][4][4];
#pragma unroll
    for (int i = 0; i < 2; i++)
#pragma unroll
        for (int j = 0; j < 4; j++)
#pragma unroll
            for (int r = 0; r < 4; r++) acc[i][j][r] = 0.f;

    const int nt = (K1 + K2) >> 5;
    const int nt1 = K1 >> 5;

    ISSUE_TILE(0);

    for (int t = 0; t < nt; t++) {
        CP_WAIT0();
        __syncthreads();
        if (t + 1 < nt) ISSUE_TILE(t + 1);

        const uint32_t AbA = sbase + (t & 1) * STAGE_BYTES;
#pragma unroll
        for (int kk = 0; kk < 4; kk++) {
            uint32_t af[2][4];
            uint32_t bf[4][2];
#pragma unroll
            for (int im = 0; im < 2; im++)
                ldsm4(af[im][0], af[im][1], af[im][2], af[im][3],
                      AbA + offA[im] + kk * 32);
#pragma unroll
            for (int p = 0; p < 2; p++)
                ldsm4(bf[2 * p][0], bf[2 * p][1], bf[2 * p + 1][0], bf[2 * p + 1][1],
                      AbA + offB[p] + kk * 32);
#pragma unroll
            for (int im = 0; im < 2; im++)
#pragma unroll
                for (int jn = 0; jn < 4; jn++)
                    mma_tf32(acc[im][jn], af[im], bf[jn]);
        }
    }

    // ---- epilogue (+ optional lr dot accumulation) ----
    float pl[2][2] = {{0.f, 0.f}, {0.f, 0.f}};
    float pr[2][2] = {{0.f, 0.f}, {0.f, 0.f}};
#pragma unroll
    for (int im = 0; im < 2; im++) {
#pragma unroll
        for (int jn = 0; jn < 4; jn++) {
            int colL = wn + jn * 8 + 2 * lk;
            if (n0l + colL >= segN) continue;
            float bias0 = 0.f, bias1 = 0.f;
            if (b1) { bias0 += b1[n0l + colL]; bias1 += b1[n0l + colL + 1]; }
            if (b2) { bias0 += b2[n0l + colL]; bias1 += b2[n0l + colL + 1]; }
#pragma unroll
            for (int half = 0; half < 2; half++) {
                int row = m0 + wm + im * 16 + lg + half * 8;
                float v0 = acc[im][jn][half * 2 + 0] + bias0;
                float v1 = acc[im][jn][half * 2 + 1] + bias1;
                if (lr_a) {
                    pl[im][half] += v0 * sAL[colL] + v1 * sAL[colL + 1];
                    pr[im][half] += v0 * sAR[colL] + v1 * sAR[colL + 1];
                }
                if (cvt) {
                    v0 = __uint_as_float(f2tf32(v0));
                    v1 = __uint_as_float(f2tf32(v1));
                }
                *reinterpret_cast<float2*>(C + (size_t)row * NTOT + n0g + colL)
                    = make_float2(v0, v1);
            }
        }
    }

    if (lr_a) {
#pragma unroll
        for (int im = 0; im < 2; im++)
#pragma unroll
            for (int half = 0; half < 2; half++) {
                pl[im][half] += __shfl_xor_sync(0xffffffffu, pl[im][half], 1);
                pl[im][half] += __shfl_xor_sync(0xffffffffu, pl[im][half], 2);
                pr[im][half] += __shfl_xor_sync(0xffffffffu, pr[im][half], 1);
                pr[im][half] += __shfl_xor_sync(0xffffffffu, pr[im][half], 2);
            }
        if (lk == 0) {
#pragma unroll
            for (int im = 0; im < 2; im++)
#pragma unroll
                for (int half = 0; half < 2; half++) {
                    int rl = wm + im * 16 + lg + half * 8;
                    sLR[0][rl][w & 1] = pl[im][half];
                    sLR[1][rl][w & 1] = pr[im][half];
                }
        }
        __syncthreads();
        int s = tid >> 7;
        int row = tid & 127;
        float v = sLR[s][row][0] + sLR[s][row][1];
        int grow = m0 + row;
        int bidx = grow >> 9;
        int ii = grow & 511;
        float* dst = s ? hr : hl;
        dst[((bidx * HEADS + nloc) << 9) + ii] = v;
    }
}

// ---------------- fast exact GELU (A&S 7.1.26 erf, abs err ~1.5e-7) ---------
__device__ __forceinline__ float gelu_fast(float x) {
    float s = x * 0.70710678118654752440f;
    float a = fabsf(s);
    float t = __frcp_rn(1.0f + 0.3275911f * a);
    float e = __expf(-a * a);
    float p = ((((1.061405429f * t - 1.453152027f) * t + 1.421413741f) * t
                - 0.284496736f) * t + 0.254829592f) * t;
    float erfv = copysignf(1.0f - p * e, s);
    return 0.5f * x * (1.0f + erfv);
}

__global__ void ln_gelu_kernel(float* __restrict__ X,
                               const float* __restrict__ g,
                               const float* __restrict__ b,
                               int D)
{
    __shared__ float sS[8], sQ[8];
    float* row = X + (size_t)blockIdx.x * D;
    const int t = threadIdx.x;
    const int w = t >> 5;
    const int lane = t & 31;

    float v0 = row[t];
    float v1 = (D > 256) ? row[t + 256] : 0.f;

    float s = v0 + v1;
    float q = v0 * v0 + v1 * v1;
#pragma unroll
    for (int o = 16; o; o >>= 1) {
        s += __shfl_xor_sync(0xffffffffu, s, o);
        q += __shfl_xor_sync(0xffffffffu, q, o);
    }
    if (lane == 0) { sS[w] = s; sQ[w] = q; }
    __syncthreads();
    float ts = 0.f, tq = 0.f;
#pragma unroll
    for (int i = 0; i < 8; i++) { ts += sS[i]; tq += sQ[i]; }
    float mean = ts / (float)D;
    float var = tq / (float)D - mean * mean;
    float rstd = rsqrtf(var + 1e-5f);

    row[t] = __uint_as_float(f2tf32(gelu_fast((v0 - mean) * rstd * g[t] + b[t])));
    if (D > 256)
        row[t + 256] = __uint_as_float(f2tf32(gelu_fast((v1 - mean) * rstd * g[t + 256] + b[t + 256])));
}

// ---------------- GAT attention: exp-factorized + tf32 MMA, double-buffered -
__global__ void gat_attn_mma_kernel(const float* __restrict__ Wh,
                                    const float* __restrict__ hl,
                                    const float* __restrict__ hr,
                                    const uint32_t* __restrict__ mb,
                                    float* __restrict__ out)
{
    __shared__ float4 sJF[NN];
    __shared__ float sA1[128], sA2[128], sNL[128];
    __shared__ uint4 sP[2][4 * 8 * 32];
    __shared__ uint32_t sW[2][32][68];
    __shared__ float sS[128];
    __shared__ float sRed[16];
    __shared__ float sMax[2];

    const int bx = blockIdx.x;
    const int it = bx & 3;
    const int h = (bx >> 2) & 3;
    const int b = bx >> 4;
    const int tid = threadIdx.x;
    const int w = tid >> 5;
    const int lane = tid & 31;
    const int lg = lane >> 2;
    const int lk = lane & 3;
    const int bh = b * HEADS + h;
    const int i0 = it * 128;

    float lv = 0.f;
    if (tid < 128) lv = hl[(bh << 9) + i0 + tid];
    float rv0 = hr[(bh << 9) + tid];
    float rv1 = hr[(bh << 9) + 256 + tid];

    float lm = (tid < 128) ? lv : -INFINITY;
    float rm = fmaxf(rv0, rv1);
#pragma unroll
    for (int o = 16; o; o >>= 1) {
        lm = fmaxf(lm, __shfl_xor_sync(0xffffffffu, lm, o));
        rm = fmaxf(rm, __shfl_xor_sync(0xffffffffu, rm, o));
    }
    if (lane == 0) { sRed[w] = lm; sRed[8 + w] = rm; }
    __syncthreads();
    if (tid == 0) {
        float L = -INFINITY, R = -INFINITY;
#pragma unroll
        for (int qq = 0; qq < 8; qq++) { L = fmaxf(L, sRed[qq]); R = fmaxf(R, sRed[8 + qq]); }
        sMax[0] = L; sMax[1] = R;
    }
    __syncthreads();
    const float Lmax = sMax[0], Rmax = sMax[1];
    const float C1 = Lmax + Rmax;

    sJF[tid]       = make_float4(rv0, expf(rv0 - Rmax), expf(0.2f * rv0), 0.f);
    sJF[tid + 256] = make_float4(rv1, expf(rv1 - Rmax), expf(0.2f * rv1), 0.f);
    if (tid < 128) {
        sA1[tid] = expf(lv - Lmax);
        sA2[tid] = expf(0.2f * lv - C1);
        sNL[tid] = -lv;
    }
    __syncthreads();

    const int r0 = w * 16 + lg;
    const int r1 = r0 + 8;
    const float A1a = sA1[r0], A2a = sA2[r0], NLa = sNL[r0];
    const float A1b = sA1[r1], A2b = sA2[r1], NLb = sNL[r1];
    const uint32_t* mrow0 = mb + ((size_t)(b << 9) + i0 + r0) * (NN / 32);
    const uint32_t* mrow1 = mb + ((size_t)(b << 9) + i0 + r1) * (NN / 32);
    float psum0 = 0.f, psum1 = 0.f;

    const int wm16 = (w >> 1) * 2;
    const int wn = (w & 1) * 32;
    float acc[2][4][4];
#pragma unroll
    for (int i = 0; i < 2; i++)
#pragma unroll
        for (int j = 0; j < 4; j++)
#pragma unroll
            for (int r = 0; r < 4; r++) acc[i][j][r] = 0.f;

    const float* whbase = Wh + (size_t)b * NN * HID + h * HD;

    for (int jt = 0; jt < 16; jt++) {
        const int buf = jt & 1;
        // ---- build phase (into buf) ----
#pragma unroll
        for (int itr = 0; itr < 2; itr++) {
            int f = tid + 256 * itr;
            int jp = f >> 4;
            int dq = (f & 15) * 4;
            float4 v = *reinterpret_cast<const float4*>(whbase + (size_t)(jt * 32 + jp) * HID + dq);
            sW[buf][jp][dq + 0] = f2tf32(v.x);
            sW[buf][jp][dq + 1] = f2tf32(v.y);
            sW[buf][jp][dq + 2] = f2tf32(v.z);
            sW[buf][jp][dq + 3] = f2tf32(v.w);
        }
        uint32_t mw0 = mrow0[jt];
        uint32_t mw1 = mrow1[jt];
#pragma unroll
        for (int kk = 0; kk < 4; kk++) {
            int c0 = kk * 8 + lk;
            int c1 = c0 + 4;
            float4 jf0 = sJF[jt * 32 + c0];
            float4 jf1 = sJF[jt * 32 + c1];
            bool cd00 = (jf0.x >= NLa), cd10 = (jf0.x >= NLb);
            bool cd01 = (jf1.x >= NLa), cd11 = (jf1.x >= NLb);
            float p00 = ((mw0 >> c0) & 1) ? (cd00 ? A1a * jf0.y : A2a * jf0.z) : 0.f;
            float p10 = ((mw1 >> c0) & 1) ? (cd10 ? A1b * jf0.y : A2b * jf0.z) : 0.f;
            float p01 = ((mw0 >> c1) & 1) ? (cd01 ? A1a * jf1.y : A2a * jf1.z) : 0.f;
            float p11 = ((mw1 >> c1) & 1) ? (cd11 ? A1b * jf1.y : A2b * jf1.z) : 0.f;
            psum0 += p00 + p01;
            psum1 += p10 + p11;
            uint4 pk;
            pk.x = f2tf32(p00);
            pk.y = f2tf32(p10);
            pk.z = f2tf32(p01);
            pk.w = f2tf32(p11);
            sP[buf][(kk * 8 + w) * 32 + lane] = pk;
        }
        __syncthreads();

        // ---- MMA phase (from buf); double-buffer makes build(jt+1) safe ----
#pragma unroll
        for (int kk = 0; kk < 4; kk++) {
            uint4 av[2];
#pragma unroll
            for (int im = 0; im < 2; im++)
                av[im] = sP[buf][(kk * 8 + wm16 + im) * 32 + lane];
#pragma unroll
            for (int jn = 0; jn < 4; jn++) {
                int nc = wn + jn * 8 + lg;
                uint32_t bf[2];
                bf[0] = sW[buf][kk * 8 + lk][nc];
                bf[1] = sW[buf][kk * 8 + 4 + lk][nc];
#pragma unroll
                for (int im = 0; im < 2; im++)
                    mma_tf32(acc[im][jn],
                             reinterpret_cast<const uint32_t*>(&av[im]), bf);
            }
        }
    }

    psum0 += __shfl_xor_sync(0xffffffffu, psum0, 1);
    psum0 += __shfl_xor_sync(0xffffffffu, psum0, 2);
    psum1 += __shfl_xor_sync(0xffffffffu, psum1, 1);
    psum1 += __shfl_xor_sync(0xffffffffu, psum1, 2);
    if (lk == 0) { sS[r0] = psum0; sS[r1] = psum1; }
    __syncthreads();

#pragma unroll
    for (int im = 0; im < 2; im++) {
#pragma unroll
        for (int half = 0; half < 2; half++) {
            int rloc = (w >> 1) * 32 + im * 16 + lg + half * 8;
            float inv = 1.f / sS[rloc];
            int grow = (b << 9) + i0 + rloc;
#pragma unroll
            for (int jn = 0; jn < 4; jn++) {
                int col = wn + jn * 8 + 2 * lk;
                float2* dst = reinterpret_cast<float2*>(out + (size_t)grow * HID + h * HD + col);
                *dst = make_float2(
                    __uint_as_float(f2tf32(acc[im][jn][half * 2 + 0] * inv)),
                    __uint_as_float(f2tf32(acc[im][jn][half * 2 + 1] * inv)));
            }
        }
    }
}

// ---------------- GRU gates -> h_temp (fp32 out + tf32 copy) ----------
__global__ void gru_kernel(const float* __restrict__ gg,
                           const float* __restrict__ hidden,
                           float* __restrict__ h_temp,
                           float* __restrict__ htc)
{
    int idx = blockIdx.x * blockDim.x + threadIdx.x;
    if (idx >= TOK * HID) return;
    int row = idx >> 8;
    int c = idx & 255;
    const float* g = gg + ((size_t)row << 10);
    float r = __frcp_rn(1.f + __expf(-g[c]));
    float z = __frcp_rn(1.f + __expf(-g[256 + c]));
    float n = tanhf(g[512 + c] + r * g[768 + c]);
    float v = (1.f - z) * n + z * hidden[idx];
    h_temp[idx] = v;
    htc[idx] = __uint_as_float(f2tf32(v));
}

// ---------------- launch ----------------
extern "C" void kernel_launch(void* const* d_in, const int* in_sizes, int n_in,
                              void* d_out, int out_size)
{
    const float* x        = (const float*)d_in[0];
    const int*   adj      = (const int*)  d_in[1];
    const float* hidden   = (const float*)d_in[2];
    const float* enc_w1   = (const float*)d_in[3];
    const float* enc_b1   = (const float*)d_in[4];
    const float* ln1_g    = (const float*)d_in[5];
    const float* ln1_b    = (const float*)d_in[6];
    const float* enc_w2   = (const float*)d_in[7];
    const float* enc_b2   = (const float*)d_in[8];
    const float* pos      = (const float*)d_in[9];
    const float* gat_w    = (const float*)d_in[10];
    const float* gat_b    = (const float*)d_in[11];
    const float* gat_a    = (const float*)d_in[12];
    const float* gat_ow   = (const float*)d_in[13];
    const float* gat_ob   = (const float*)d_in[14];
    const float* skip_w   = (const float*)d_in[15];
    const float* skip_b   = (const float*)d_in[16];
    const float* gru_wih  = (const float*)d_in[17];
    const float* gru_bih  = (const float*)d_in[18];
    const float* gru_whh  = (const float*)d_in[19];
    const float* gru_bhh  = (const float*)d_in[20];
    const float* dec_w1   = (const float*)d_in[21];
    const float* dec_b1   = (const float*)d_in[22];
    const float* ln2_g    = (const float*)d_in[23];
    const float* ln2_b    = (const float*)d_in[24];
    const float* dec_w2   = (const float*)d_in[25];
    const float* dec_b2   = (const float*)d_in[26];

    float* out = (float*)d_out;
    float* q_out = out;
    float* h_temp_out = out + (size_t)TOK * ACT;

    float *h1, *hsp, *Wh, *hl, *hr, *aout, *hattn, *gg, *q;
    float *xc, *hidc, *htc, *wc;
    uint32_t* mbits;
    cudaGetSymbolAddress((void**)&h1,    g_h1);
    cudaGetSymbolAddress((void**)&hsp,   g_hsp);
    cudaGetSymbolAddress((void**)&Wh,    g_Wh);
    cudaGetSymbolAddress((void**)&hl,    g_hl);
    cudaGetSymbolAddress((void**)&hr,    g_hr);
    cudaGetSymbolAddress((void**)&aout,  g_aout);
    cudaGetSymbolAddress((void**)&hattn, g_hattn);
    cudaGetSymbolAddress((void**)&gg,    g_gg);
    cudaGetSymbolAddress((void**)&q,     g_q);
    cudaGetSymbolAddress((void**)&xc,    g_xc);
    cudaGetSymbolAddress((void**)&hidc,  g_hidc);
    cudaGetSymbolAddress((void**)&htc,   g_htc);
    cudaGetSymbolAddress((void**)&wc,    g_wc);
    cudaGetSymbolAddress((void**)&mbits, g_mbits);

    cudaFuncSetAttribute(gemm_tf32_kernel,
                         cudaFuncAttributeMaxDynamicSharedMemorySize,
                         GEMM_SMEM_BYTES);

    const int MB = TOK / 128;
    const size_t SH = GEMM_SMEM_BYTES;
    Seg Z = { nullptr, nullptr, nullptr, nullptr, nullptr, nullptr, 0, 0, 0, 0 };

    prep_kernel<<<CVT_BLOCKS + TOK, 512>>>(
        x, hidden, enc_w1, enc_w2, gat_w, gat_ow, skip_w, gru_wih, gru_whh,
        dec_w1, dec_w2, xc, hidc, wc, adj, mbits);

    // encoder
    {
        Seg s = { xc, nullptr, wc + WC_ENC1, nullptr, enc_b1, nullptr, IND, 0, 0, HID2 };
        gemm_tf32_kernel<<<dim3(8, MB), 256, SH>>>(s, Z, Z, 8, 8, h1, HID2, TOK,
                                                   nullptr, nullptr, nullptr);
    }
    ln_gelu_kernel<<<TOK, 256>>>(h1, ln1_g, ln1_b, HID2);
    {
        Seg s = { h1, nullptr, wc + WC_ENC2, nullptr, enc_b2, pos, HID2, 0, 1, HID };
        gemm_tf32_kernel<<<dim3(4, MB), 256, SH>>>(s, Z, Z, 4, 4, hsp, HID, TOK,
                                                   nullptr, nullptr, nullptr);
    }

    // GAT projection + fused l/r scores
    {
        Seg s = { hsp, nullptr, wc + WC_GAT, nullptr, gat_b, nullptr, HID, 0, 1, HID };
        gemm_tf32_kernel<<<dim3(4, MB), 256, SH>>>(s, Z, Z, 4, 4, Wh, HID, TOK,
                                                   gat_a, hl, hr);
    }
    gat_attn_mma_kernel<<<BB * HEADS * 4, 256>>>(Wh, hl, hr, mbits, aout);

    // fused out-proj + skip
    {
        Seg s = { aout, hsp, wc + WC_OW, wc + WC_SKIP, gat_ob, skip_b, HID, HID, 1, HID };
        gemm_tf32_kernel<<<dim3(4, MB), 256, SH>>>(s, Z, Z, 4, 4, hattn, HID, TOK,
                                                   nullptr, nullptr, nullptr);
    }

    // merged GRU GEMM
    {
        Seg s0 = { hattn, hidc, wc + WC_WIH, wc + WC_WHH, gru_bih, gru_bhh,
                   HID, HID, 0, HID2 };
        Seg s1 = { hattn, nullptr, wc + WC_WIH + 2 * HID * HID, nullptr,
                   gru_bih + 2 * HID, nullptr, HID, 0, 0, HID };
        Seg s2 = { hidc, nullptr, wc + WC_WHH + 2 * HID * HID, nullptr,
                   gru_bhh + 2 * HID, nullptr, HID, 0, 0, HID };
        gemm_tf32_kernel<<<dim3(16, MB), 256, SH>>>(s0, s1, s2, 8, 12, gg, 1024, TOK,
                                                    nullptr, nullptr, nullptr);
    }
    gru_kernel<<<(TOK * HID + 255) / 256, 256>>>(gg, hidden, h_temp_out, htc);

    // decoder
    {
        Seg s = { htc, nullptr, wc + WC_DEC1, nullptr, dec_b1, nullptr, HID, 0, 0, HID };
        gemm_tf32_kernel<<<dim3(4, MB), 256, SH>>>(s, Z, Z, 4, 4, q, HID, TOK,
                                                   nullptr, nullptr, nullptr);
    }
    ln_gelu_kernel<<<TOK, 256>>>(q, ln2_g, ln2_b, HID);
    {
        Seg s = { q, nullptr, wc + WC_DEC2, nullptr, dec_b2, nullptr, HID, 0, 0, ACT };
        gemm_tf32_kernel<<<dim3(1, MB), 256, SH>>>(s, Z, Z, 1, 1, q_out, ACT, TOK,
                                                   nullptr, nullptr, nullptr);
    }
}